// round 1
// baseline (speedup 1.0000x reference)
#include <cuda_runtime.h>
#include <math.h>

// ---------------------------------------------------------------------------
// SelfAttention: out = softmax((xWq^T)(xWk^T)^T / sqrt(1024)) (xWv^T) + xWv^T
// x: [4, 2048, 1024] fp32; Wq/Wk/Wv: [1024, 1024] fp32 (out,in); out fp32.
// Round 1: correct fp32 baseline. 4 kernels:
//   gemm_nt      : C = scale * A[M,K] * B[N,K]^T   (QKV proj + QK^T scores)
//   softmax_rows : row-wise softmax over 2048 cols
//   gemm_nn_res  : C = A[M,K] * B[K,N] + R[M,N]    (S*V + V residual)
// Scratch: __device__ globals (no allocation).
// ---------------------------------------------------------------------------

#define BM 128
#define BN 128
#define BK 16
#define THREADS 256

static const int BATCH = 4;
static const int SEQ   = 2048;
static const int DIM   = 1024;

__device__ float g_q[4 * 2048 * 1024];
__device__ float g_k[4 * 2048 * 1024];
__device__ float g_v[4 * 2048 * 1024];
__device__ float g_s[4ll * 2048 * 2048];

// C[M,N] = scale * A[M,K] * B[N,K]^T  (both A and B are K-contiguous)
__global__ __launch_bounds__(THREADS) void gemm_nt(
    const float* __restrict__ A, const float* __restrict__ B, float* __restrict__ C,
    int M, int N, int K, float scale,
    long long strideA, long long strideB, long long strideC)
{
    A += (long long)blockIdx.z * strideA;
    B += (long long)blockIdx.z * strideB;
    C += (long long)blockIdx.z * strideC;

    __shared__ float As[BK][BM];
    __shared__ float Bs[BK][BN];

    const int tid = threadIdx.x;
    const int m0 = blockIdx.y * BM;
    const int n0 = blockIdx.x * BN;
    const int ty = tid >> 4;   // 0..15
    const int tx = tid & 15;   // 0..15

    float acc[8][8] = {};

    for (int k0 = 0; k0 < K; k0 += BK) {
        // Load A tile [BM x BK] and B tile [BN x BK], transpose into smem [BK][*]
        #pragma unroll
        for (int i = 0; i < 2; i++) {
            int t   = tid + i * 256;        // 0..511
            int row = t >> 2;               // 0..127
            int kv  = (t & 3) << 2;         // 0,4,8,12
            float4 va = *(const float4*)&A[(long long)(m0 + row) * K + k0 + kv];
            As[kv + 0][row] = va.x; As[kv + 1][row] = va.y;
            As[kv + 2][row] = va.z; As[kv + 3][row] = va.w;
            float4 vb = *(const float4*)&B[(long long)(n0 + row) * K + k0 + kv];
            Bs[kv + 0][row] = vb.x; Bs[kv + 1][row] = vb.y;
            Bs[kv + 2][row] = vb.z; Bs[kv + 3][row] = vb.w;
        }
        __syncthreads();

        #pragma unroll
        for (int k = 0; k < BK; k++) {
            float ar[8], br[8];
            #pragma unroll
            for (int i = 0; i < 8; i++) ar[i] = As[k][ty * 8 + i];
            #pragma unroll
            for (int j = 0; j < 8; j++) br[j] = Bs[k][tx * 8 + j];
            #pragma unroll
            for (int i = 0; i < 8; i++)
                #pragma unroll
                for (int j = 0; j < 8; j++)
                    acc[i][j] = fmaf(ar[i], br[j], acc[i][j]);
        }
        __syncthreads();
    }

    #pragma unroll
    for (int i = 0; i < 8; i++) {
        long long row = m0 + ty * 8 + i;
        #pragma unroll
        for (int j = 0; j < 8; j += 4) {
            float4 o;
            o.x = acc[i][j + 0] * scale;
            o.y = acc[i][j + 1] * scale;
            o.z = acc[i][j + 2] * scale;
            o.w = acc[i][j + 3] * scale;
            *(float4*)&C[row * N + n0 + tx * 8 + j] = o;
        }
    }
}

// C[M,N] = A[M,K] * B[K,N] + R[M,N]   (A K-contiguous, B N-contiguous)
__global__ __launch_bounds__(THREADS) void gemm_nn_res(
    const float* __restrict__ A, const float* __restrict__ B,
    const float* __restrict__ R, float* __restrict__ C,
    int M, int N, int K,
    long long strideA, long long strideB, long long strideC)
{
    A += (long long)blockIdx.z * strideA;
    B += (long long)blockIdx.z * strideB;
    R += (long long)blockIdx.z * strideB;   // residual = V, same stride as B
    C += (long long)blockIdx.z * strideC;

    __shared__ float As[BK][BM];
    __shared__ float Bs[BK][BN];

    const int tid = threadIdx.x;
    const int m0 = blockIdx.y * BM;
    const int n0 = blockIdx.x * BN;
    const int ty = tid >> 4;
    const int tx = tid & 15;

    float acc[8][8] = {};

    for (int k0 = 0; k0 < K; k0 += BK) {
        #pragma unroll
        for (int i = 0; i < 2; i++) {
            int t   = tid + i * 256;
            // A tile [BM x BK] -> transposed store
            int row = t >> 2;
            int kv  = (t & 3) << 2;
            float4 va = *(const float4*)&A[(long long)(m0 + row) * K + k0 + kv];
            As[kv + 0][row] = va.x; As[kv + 1][row] = va.y;
            As[kv + 2][row] = va.z; As[kv + 3][row] = va.w;
            // B tile [BK x BN] -> direct store (N-contiguous)
            int brow = t >> 5;             // 0..15
            int nv   = (t & 31) << 2;      // 0..124
            float4 vb = *(const float4*)&B[(long long)(k0 + brow) * N + n0 + nv];
            *(float4*)&Bs[brow][nv] = vb;
        }
        __syncthreads();

        #pragma unroll
        for (int k = 0; k < BK; k++) {
            float ar[8], br[8];
            #pragma unroll
            for (int i = 0; i < 8; i++) ar[i] = As[k][ty * 8 + i];
            #pragma unroll
            for (int j = 0; j < 8; j++) br[j] = Bs[k][tx * 8 + j];
            #pragma unroll
            for (int i = 0; i < 8; i++)
                #pragma unroll
                for (int j = 0; j < 8; j++)
                    acc[i][j] = fmaf(ar[i], br[j], acc[i][j]);
        }
        __syncthreads();
    }

    #pragma unroll
    for (int i = 0; i < 8; i++) {
        long long row = m0 + ty * 8 + i;
        #pragma unroll
        for (int j = 0; j < 8; j += 4) {
            float4 r = *(const float4*)&R[row * N + n0 + tx * 8 + j];
            float4 o;
            o.x = acc[i][j + 0] + r.x;
            o.y = acc[i][j + 1] + r.y;
            o.z = acc[i][j + 2] + r.z;
            o.w = acc[i][j + 3] + r.w;
            *(float4*)&C[row * N + n0 + tx * 8 + j] = o;
        }
    }
}

// In-place row softmax; ncols == 2048, 256 threads x 8 elems each.
__global__ __launch_bounds__(256) void softmax_rows(float* __restrict__ S, int ncols)
{
    long long row = blockIdx.x;
    float* p = S + row * ncols;
    int tid = threadIdx.x;

    __shared__ float red[256];

    float v[8];
    float mx = -INFINITY;
    #pragma unroll
    for (int i = 0; i < 8; i++) {
        v[i] = p[tid + i * 256];
        mx = fmaxf(mx, v[i]);
    }
    red[tid] = mx;
    __syncthreads();
    #pragma unroll
    for (int s = 128; s > 0; s >>= 1) {
        if (tid < s) red[tid] = fmaxf(red[tid], red[tid + s]);
        __syncthreads();
    }
    mx = red[0];
    __syncthreads();

    float sum = 0.f;
    #pragma unroll
    for (int i = 0; i < 8; i++) {
        v[i] = __expf(v[i] - mx);
        sum += v[i];
    }
    red[tid] = sum;
    __syncthreads();
    #pragma unroll
    for (int s = 128; s > 0; s >>= 1) {
        if (tid < s) red[tid] += red[tid + s];
        __syncthreads();
    }
    float inv = 1.0f / red[0];
    #pragma unroll
    for (int i = 0; i < 8; i++) p[tid + i * 256] = v[i] * inv;
}

extern "C" void kernel_launch(void* const* d_in, const int* in_sizes, int n_in,
                              void* d_out, int out_size)
{
    const float* x  = (const float*)d_in[0];
    const float* Wq = (const float*)d_in[1];
    const float* Wk = (const float*)d_in[2];
    const float* Wv = (const float*)d_in[3];
    float* out = (float*)d_out;

    float *q, *k, *v, *s;
    cudaGetSymbolAddress((void**)&q, g_q);
    cudaGetSymbolAddress((void**)&k, g_k);
    cudaGetSymbolAddress((void**)&v, g_v);
    cudaGetSymbolAddress((void**)&s, g_s);

    const int M = BATCH * SEQ;  // 8192
    dim3 blk(THREADS);

    // QKV projections: [8192,1024] = x[8192,1024] @ W[1024,1024]^T
    dim3 gQKV(DIM / BN, M / BM);  // (8, 64)
    gemm_nt<<<gQKV, blk>>>(x, Wq, q, M, DIM, DIM, 1.0f, 0, 0, 0);
    gemm_nt<<<gQKV, blk>>>(x, Wk, k, M, DIM, DIM, 1.0f, 0, 0, 0);
    gemm_nt<<<gQKV, blk>>>(x, Wv, v, M, DIM, DIM, 1.0f, 0, 0, 0);

    // Scores: per batch, S = (1/32) * q @ k^T   [2048, 2048]
    dim3 gS(SEQ / BN, SEQ / BM, BATCH);  // (16, 16, 4)
    gemm_nt<<<gS, blk>>>(q, k, s, SEQ, SEQ, DIM, 0.03125f,
                         (long long)SEQ * DIM, (long long)SEQ * DIM,
                         (long long)SEQ * SEQ);

    // Row softmax over all 4*2048 rows
    softmax_rows<<<BATCH * SEQ, 256>>>(s, SEQ);

    // Output: att = S @ v + v   [2048, 1024] per batch
    dim3 gO(DIM / BN, SEQ / BM, BATCH);  // (8, 16, 4)
    gemm_nn_res<<<gO, blk>>>(s, v, v, out, SEQ, DIM, SEQ,
                             (long long)SEQ * SEQ, (long long)SEQ * DIM,
                             (long long)SEQ * DIM);
}

// round 3
// speedup vs baseline: 2.8399x; 2.8399x over previous
#include <cuda_runtime.h>
#include <cstdint>
#include <math.h>

// ---------------------------------------------------------------------------
// SelfAttention on GB300 (sm_103a host, compute_103 PTX target), Round 3:
// tensor cores via baseline PTX mma.sync m16n8k8 tf32 (tcgen05 is rejected by
// this toolchain's compute_103 target).
//
// out = softmax((xWq^T)(xWk^T)^T / 32) @ (xWv^T) + (xWv^T)
// All GEMMs as NT: C[M,N] = scale * A[M,K] * B[N,K]^T (+R).
// CTA 128x128x32, 8 warps (2x4), warp tile 64x32, double-buffered cp.async.
// All mma operands pre-rounded to tf32 (cvt.rna) for unbiased error.
// ---------------------------------------------------------------------------

#define BATCH 4
#define SEQ   2048
#define DIM   1024

#define BM 128
#define BN 128
#define BK 32
#define LDS_ROW 36                       // BK + 4 pad (floats)
#define STAGE_FLOATS (2 * BM * LDS_ROW)  // A + B per stage = 9216 floats
#define SMEM_BYTES (2 * STAGE_FLOATS * 4)  // 73728 B

__device__ float g_q [(size_t)BATCH * SEQ * DIM];
__device__ float g_k [(size_t)BATCH * SEQ * DIM];
__device__ float g_v [(size_t)BATCH * SEQ * DIM];
__device__ float g_vt[(size_t)BATCH * DIM * SEQ];
__device__ float g_s [(size_t)BATCH * SEQ * SEQ];
__device__ float g_xr[(size_t)BATCH * SEQ * DIM];
__device__ float g_wq[(size_t)DIM * DIM];
__device__ float g_wk[(size_t)DIM * DIM];
__device__ float g_wv[(size_t)DIM * DIM];

__device__ __forceinline__ float round_tf32(float x) {
    uint32_t u;
    asm("cvt.rna.tf32.f32 %0, %1;" : "=r"(u) : "f"(x));
    return __uint_as_float(u);
}

#define CP16(dst_u32, src_ptr) \
    asm volatile("cp.async.cg.shared.global [%0], [%1], 16;" :: "r"(dst_u32), "l"(src_ptr) : "memory")
#define CP_COMMIT() asm volatile("cp.async.commit_group;" ::: "memory")
#define CP_WAIT(n)  asm volatile("cp.async.wait_group %0;" :: "n"(n) : "memory")

// ---------------------------------------------------------------------------
// C[M,N] = scale * A[M,K] * B[N,K]^T (+ R), tf32 tensor cores.
// ---------------------------------------------------------------------------
__global__ void __launch_bounds__(256, 2) mma_gemm_nt(
    const float* __restrict__ A, const float* __restrict__ B,
    const float* __restrict__ R, float* __restrict__ C,
    int lda, int ldb, int ldc, int KT, float scale, int round_out,
    long long sA, long long sB, long long sR, long long sC)
{
    extern __shared__ float sm[];

    const int tid  = threadIdx.x;
    const int lane = tid & 31;
    const int wid  = tid >> 5;
    const int wm   = wid >> 2;   // 0..1  (64-row slab)
    const int wn   = wid & 3;    // 0..3  (32-col slab)
    const int g    = lane >> 2;  // 0..7
    const int t    = lane & 3;   // 0..3

    A += (long long)blockIdx.z * sA + (long long)(blockIdx.y * BM) * lda;
    B += (long long)blockIdx.z * sB + (long long)(blockIdx.x * BN) * ldb;

    const uint32_t sm_u32 = (uint32_t)__cvta_generic_to_shared(sm);

    float acc[4][4][4] = {};

    // loader: 256 threads, 4 float4 for A + 4 for B per stage
    auto load_stage = [&](int kt, int s) {
        const uint32_t stA = sm_u32 + (uint32_t)s * (STAGE_FLOATS * 4);
        const uint32_t stB = stA + BM * LDS_ROW * 4;
        const int k0 = kt * BK;
        #pragma unroll
        for (int i = 0; i < 4; i++) {
            int f   = tid * 4 + i;        // 0..1023
            int row = f >> 3;             // 0..127
            int c4  = (f & 7) << 2;       // 0,4,..,28
            CP16(stA + (uint32_t)(row * LDS_ROW + c4) * 4, A + (long long)row * lda + k0 + c4);
            CP16(stB + (uint32_t)(row * LDS_ROW + c4) * 4, B + (long long)row * ldb + k0 + c4);
        }
        CP_COMMIT();
    };

    load_stage(0, 0);

    for (int kt = 0; kt < KT; kt++) {
        const int cur = kt & 1;
        if (kt + 1 < KT) { load_stage(kt + 1, cur ^ 1); CP_WAIT(1); }
        else             { CP_WAIT(0); }
        __syncthreads();

        const float* pA = sm + cur * STAGE_FLOATS + (wm * 64) * LDS_ROW;
        const float* pB = sm + cur * STAGE_FLOATS + BM * LDS_ROW + (wn * 32) * LDS_ROW;

        #pragma unroll
        for (int kk = 0; kk < 4; kk++) {
            const int kb = kk * 8;
            uint32_t af[4][4], bf[4][2];
            #pragma unroll
            for (int mt = 0; mt < 4; mt++) {
                const float* r0 = pA + (mt * 16 + g) * LDS_ROW + kb + t;
                const float* r1 = r0 + 8 * LDS_ROW;
                af[mt][0] = __float_as_uint(r0[0]);
                af[mt][1] = __float_as_uint(r1[0]);
                af[mt][2] = __float_as_uint(r0[4]);
                af[mt][3] = __float_as_uint(r1[4]);
            }
            #pragma unroll
            for (int nt = 0; nt < 4; nt++) {
                const float* c0 = pB + (nt * 8 + g) * LDS_ROW + kb + t;
                bf[nt][0] = __float_as_uint(c0[0]);
                bf[nt][1] = __float_as_uint(c0[4]);
            }
            #pragma unroll
            for (int mt = 0; mt < 4; mt++)
                #pragma unroll
                for (int nt = 0; nt < 4; nt++)
                    asm volatile(
                        "mma.sync.aligned.m16n8k8.row.col.f32.tf32.tf32.f32 "
                        "{%0,%1,%2,%3}, {%4,%5,%6,%7}, {%8,%9}, {%0,%1,%2,%3};"
                        : "+f"(acc[mt][nt][0]), "+f"(acc[mt][nt][1]),
                          "+f"(acc[mt][nt][2]), "+f"(acc[mt][nt][3])
                        : "r"(af[mt][0]), "r"(af[mt][1]), "r"(af[mt][2]), "r"(af[mt][3]),
                          "r"(bf[nt][0]), "r"(bf[nt][1]));
        }
        __syncthreads();
    }

    // epilogue
    float* Cb = C + (long long)blockIdx.z * sC
                  + (long long)(blockIdx.y * BM + wm * 64) * ldc + blockIdx.x * BN + wn * 32;
    const float* Rb = R ? (R + (long long)blockIdx.z * sR
                  + (long long)(blockIdx.y * BM + wm * 64) * ldc + blockIdx.x * BN + wn * 32)
                        : nullptr;

    #pragma unroll
    for (int mt = 0; mt < 4; mt++) {
        #pragma unroll
        for (int nt = 0; nt < 4; nt++) {
            const int r0 = mt * 16 + g;
            const int c0 = nt * 8 + t * 2;
            float v0 = acc[mt][nt][0] * scale;
            float v1 = acc[mt][nt][1] * scale;
            float v2 = acc[mt][nt][2] * scale;
            float v3 = acc[mt][nt][3] * scale;
            if (Rb) {
                v0 += Rb[(long long)r0 * ldc + c0];
                v1 += Rb[(long long)r0 * ldc + c0 + 1];
                v2 += Rb[(long long)(r0 + 8) * ldc + c0];
                v3 += Rb[(long long)(r0 + 8) * ldc + c0 + 1];
            }
            if (round_out) {
                v0 = round_tf32(v0); v1 = round_tf32(v1);
                v2 = round_tf32(v2); v3 = round_tf32(v3);
            }
            *(float2*)&Cb[(long long)r0 * ldc + c0]       = make_float2(v0, v1);
            *(float2*)&Cb[(long long)(r0 + 8) * ldc + c0] = make_float2(v2, v3);
        }
    }
}

// ---------------- round fp32 array to tf32 (rna) ----------------
__global__ void __launch_bounds__(256) round_arr(const float* __restrict__ in,
                                                 float* __restrict__ out)
{
    long long i = ((long long)blockIdx.x * 256 + threadIdx.x) * 4;
    float4 v = *(const float4*)&in[i];
    v.x = round_tf32(v.x); v.y = round_tf32(v.y);
    v.z = round_tf32(v.z); v.w = round_tf32(v.w);
    *(float4*)&out[i] = v;
}

// ---------------- transpose: vt[b][n][j] = v[b][j][n] ----------------
__global__ void __launch_bounds__(256) transpose_v(const float* __restrict__ v,
                                                   float* __restrict__ vt)
{
    __shared__ float t[32][33];
    const long long bi = (long long)blockIdx.z * SEQ * DIM;
    const long long bo = (long long)blockIdx.z * DIM * SEQ;
    int x = blockIdx.x * 32 + threadIdx.x;   // n
    int y = blockIdx.y * 32 + threadIdx.y;   // j
    #pragma unroll
    for (int i = 0; i < 32; i += 8)
        t[threadIdx.y + i][threadIdx.x] = v[bi + (long long)(y + i) * DIM + x];
    __syncthreads();
    int xo = blockIdx.y * 32 + threadIdx.x;  // j
    int yo = blockIdx.x * 32 + threadIdx.y;  // n
    #pragma unroll
    for (int i = 0; i < 32; i += 8)
        vt[bo + (long long)(yo + i) * SEQ + xo] = t[threadIdx.x][threadIdx.y + i];
}

// ---------------- row softmax (2048 cols), writes tf32-rounded probs --------
__global__ void __launch_bounds__(256) softmax_rows(float* __restrict__ S)
{
    long long row = blockIdx.x;
    float* p = S + row * SEQ;
    int tid = threadIdx.x;
    __shared__ float red[256];

    float v[8];
    float mx = -INFINITY;
    #pragma unroll
    for (int i = 0; i < 8; i++) { v[i] = p[tid + i * 256]; mx = fmaxf(mx, v[i]); }
    red[tid] = mx; __syncthreads();
    #pragma unroll
    for (int s = 128; s > 0; s >>= 1) { if (tid < s) red[tid] = fmaxf(red[tid], red[tid + s]); __syncthreads(); }
    mx = red[0]; __syncthreads();

    float sum = 0.f;
    #pragma unroll
    for (int i = 0; i < 8; i++) { v[i] = __expf(v[i] - mx); sum += v[i]; }
    red[tid] = sum; __syncthreads();
    #pragma unroll
    for (int s = 128; s > 0; s >>= 1) { if (tid < s) red[tid] += red[tid + s]; __syncthreads(); }
    float inv = 1.0f / red[0];
    #pragma unroll
    for (int i = 0; i < 8; i++) p[tid + i * 256] = round_tf32(v[i] * inv);
}

extern "C" void kernel_launch(void* const* d_in, const int* in_sizes, int n_in,
                              void* d_out, int out_size)
{
    const float* x  = (const float*)d_in[0];
    const float* Wq = (const float*)d_in[1];
    const float* Wk = (const float*)d_in[2];
    const float* Wv = (const float*)d_in[3];
    float* out = (float*)d_out;

    float *q, *k, *v, *vt, *s, *xr, *wq, *wk, *wv;
    cudaGetSymbolAddress((void**)&q,  g_q);
    cudaGetSymbolAddress((void**)&k,  g_k);
    cudaGetSymbolAddress((void**)&v,  g_v);
    cudaGetSymbolAddress((void**)&vt, g_vt);
    cudaGetSymbolAddress((void**)&s,  g_s);
    cudaGetSymbolAddress((void**)&xr, g_xr);
    cudaGetSymbolAddress((void**)&wq, g_wq);
    cudaGetSymbolAddress((void**)&wk, g_wk);
    cudaGetSymbolAddress((void**)&wv, g_wv);

    cudaFuncSetAttribute(mma_gemm_nt, cudaFuncAttributeMaxDynamicSharedMemorySize, SMEM_BYTES);

    const int M = BATCH * SEQ;   // 8192

    // Pre-round inputs to tf32 (rna, unbiased)
    round_arr<<<(M * DIM) / 1024, 256>>>(x, xr);
    round_arr<<<(DIM * DIM) / 1024, 256>>>(Wq, wq);
    round_arr<<<(DIM * DIM) / 1024, 256>>>(Wk, wk);
    round_arr<<<(DIM * DIM) / 1024, 256>>>(Wv, wv);

    // QKV projections: [8192,1024] = xr @ W^T, K=1024 (32 k-tiles), round outputs
    dim3 gP(DIM / BN, M / BM, 1);
    mma_gemm_nt<<<gP, 256, SMEM_BYTES>>>(xr, wq, nullptr, q, DIM, DIM, DIM, 32, 1.0f, 1, 0, 0, 0, 0);
    mma_gemm_nt<<<gP, 256, SMEM_BYTES>>>(xr, wk, nullptr, k, DIM, DIM, DIM, 32, 1.0f, 1, 0, 0, 0, 0);
    mma_gemm_nt<<<gP, 256, SMEM_BYTES>>>(xr, wv, nullptr, v, DIM, DIM, DIM, 32, 1.0f, 1, 0, 0, 0, 0);

    // V transpose for PV gemm
    dim3 gT(DIM / 32, SEQ / 32, BATCH);
    transpose_v<<<gT, dim3(32, 8)>>>(v, vt);

    // Scores: per batch S = (1/32) q @ k^T, [2048,2048], K=1024
    dim3 gS(SEQ / BN, SEQ / BM, BATCH);
    mma_gemm_nt<<<gS, 256, SMEM_BYTES>>>(q, k, nullptr, s, DIM, DIM, SEQ, 32, 0.03125f, 0,
                                         (long long)SEQ * DIM, (long long)SEQ * DIM, 0,
                                         (long long)SEQ * SEQ);

    // Softmax (writes tf32-rounded probabilities)
    softmax_rows<<<BATCH * SEQ, 256>>>(s);

    // Output: att = S @ v + v  ->  NT with B = vt [1024 x 2048], K=2048 (64 k-tiles)
    dim3 gO(DIM / BN, SEQ / BM, BATCH);
    mma_gemm_nt<<<gO, 256, SMEM_BYTES>>>(s, vt, v, out, SEQ, SEQ, DIM, 64, 1.0f, 0,
                                         (long long)SEQ * SEQ, (long long)DIM * SEQ,
                                         (long long)SEQ * DIM, (long long)SEQ * DIM);
}

// round 4
// speedup vs baseline: 3.7807x; 1.3313x over previous
#include <cuda_runtime.h>
#include <cstdint>
#include <math.h>

// ---------------------------------------------------------------------------
// SelfAttention on GB300 (compute_103 PTX target), Round 4:
// mma.sync m16n8k8 tf32, CTA tile 256x128x32, warp tile 64x64 (4x8 frags),
// double-buffered cp.async. 8 warps, ~1.0 LDS per mma.
//
// out = softmax((xWq^T)(xWk^T)^T / 32) @ (xWv^T) + (xWv^T)
// All GEMMs as NT: C[M,N] = scale * A[M,K] * B[N,K]^T (+R).
// ---------------------------------------------------------------------------

#define BATCH 4
#define SEQ   2048
#define DIM   1024

#define BM 256
#define BN 128
#define BK 32
#define LDS_ROW 36                                  // BK + 4 pad (floats)
#define A_FLOATS (BM * LDS_ROW)                     // 9216
#define B_FLOATS (BN * LDS_ROW)                     // 4608
#define STAGE_FLOATS (A_FLOATS + B_FLOATS)          // 13824
#define SMEM_BYTES (2 * STAGE_FLOATS * 4)           // 110592 B

__device__ float g_q [(size_t)BATCH * SEQ * DIM];
__device__ float g_k [(size_t)BATCH * SEQ * DIM];
__device__ float g_v [(size_t)BATCH * SEQ * DIM];
__device__ float g_vt[(size_t)BATCH * DIM * SEQ];
__device__ float g_s [(size_t)BATCH * SEQ * SEQ];
__device__ float g_xr[(size_t)BATCH * SEQ * DIM];
__device__ float g_wq[(size_t)DIM * DIM];
__device__ float g_wk[(size_t)DIM * DIM];
__device__ float g_wv[(size_t)DIM * DIM];

__device__ __forceinline__ float round_tf32(float x) {
    uint32_t u;
    asm("cvt.rna.tf32.f32 %0, %1;" : "=r"(u) : "f"(x));
    return __uint_as_float(u);
}

#define CP16(dst_u32, src_ptr) \
    asm volatile("cp.async.cg.shared.global [%0], [%1], 16;" :: "r"(dst_u32), "l"(src_ptr) : "memory")
#define CP_COMMIT() asm volatile("cp.async.commit_group;" ::: "memory")
#define CP_WAIT(n)  asm volatile("cp.async.wait_group %0;" :: "n"(n) : "memory")

// ---------------------------------------------------------------------------
// C[M,N] = scale * A[M,K] * B[N,K]^T (+ R), tf32 tensor cores.
// ---------------------------------------------------------------------------
__global__ void __launch_bounds__(256, 1) mma_gemm_nt(
    const float* __restrict__ A, const float* __restrict__ B,
    const float* __restrict__ R, float* __restrict__ C,
    int lda, int ldb, int ldc, int KT, float scale, int round_out,
    long long sA, long long sB, long long sR, long long sC)
{
    extern __shared__ float sm[];

    const int tid  = threadIdx.x;
    const int lane = tid & 31;
    const int wid  = tid >> 5;
    const int wm   = wid >> 1;   // 0..3  (64-row slab)
    const int wn   = wid & 1;    // 0..1  (64-col slab)
    const int g    = lane >> 2;  // 0..7
    const int t    = lane & 3;   // 0..3

    A += (long long)blockIdx.z * sA + (long long)(blockIdx.y * BM) * lda;
    B += (long long)blockIdx.z * sB + (long long)(blockIdx.x * BN) * ldb;

    const uint32_t sm_u32 = (uint32_t)__cvta_generic_to_shared(sm);

    float acc[4][8][4] = {};

    // loader: 256 threads; A tile 256x32 = 2048 float4 (8/thr), B 128x32 = 1024 (4/thr)
    auto load_stage = [&](int kt, int s) {
        const uint32_t stA = sm_u32 + (uint32_t)s * (STAGE_FLOATS * 4);
        const uint32_t stB = stA + A_FLOATS * 4;
        const int k0 = kt * BK;
        #pragma unroll
        for (int i = 0; i < 8; i++) {
            int f   = i * 256 + tid;      // 0..2047
            int row = f >> 3;             // 0..255
            int c4  = (f & 7) << 2;       // 0,4,..,28
            CP16(stA + (uint32_t)(row * LDS_ROW + c4) * 4, A + (long long)row * lda + k0 + c4);
        }
        #pragma unroll
        for (int i = 0; i < 4; i++) {
            int f   = i * 256 + tid;      // 0..1023
            int row = f >> 3;             // 0..127
            int c4  = (f & 7) << 2;
            CP16(stB + (uint32_t)(row * LDS_ROW + c4) * 4, B + (long long)row * ldb + k0 + c4);
        }
        CP_COMMIT();
    };

    load_stage(0, 0);

    for (int kt = 0; kt < KT; kt++) {
        const int cur = kt & 1;
        if (kt + 1 < KT) { load_stage(kt + 1, cur ^ 1); CP_WAIT(1); }
        else             { CP_WAIT(0); }
        __syncthreads();

        const float* pA = sm + cur * STAGE_FLOATS + (wm * 64) * LDS_ROW;
        const float* pB = sm + cur * STAGE_FLOATS + A_FLOATS + (wn * 64) * LDS_ROW;

        #pragma unroll
        for (int kk = 0; kk < 4; kk++) {
            const int kb = kk * 8;
            uint32_t af[4][4], bf[8][2];
            #pragma unroll
            for (int mt = 0; mt < 4; mt++) {
                const float* r0 = pA + (mt * 16 + g) * LDS_ROW + kb + t;
                const float* r1 = r0 + 8 * LDS_ROW;
                af[mt][0] = __float_as_uint(r0[0]);
                af[mt][1] = __float_as_uint(r1[0]);
                af[mt][2] = __float_as_uint(r0[4]);
                af[mt][3] = __float_as_uint(r1[4]);
            }
            #pragma unroll
            for (int nt = 0; nt < 8; nt++) {
                const float* c0 = pB + (nt * 8 + g) * LDS_ROW + kb + t;
                bf[nt][0] = __float_as_uint(c0[0]);
                bf[nt][1] = __float_as_uint(c0[4]);
            }
            #pragma unroll
            for (int mt = 0; mt < 4; mt++)
                #pragma unroll
                for (int nt = 0; nt < 8; nt++)
                    asm volatile(
                        "mma.sync.aligned.m16n8k8.row.col.f32.tf32.tf32.f32 "
                        "{%0,%1,%2,%3}, {%4,%5,%6,%7}, {%8,%9}, {%0,%1,%2,%3};"
                        : "+f"(acc[mt][nt][0]), "+f"(acc[mt][nt][1]),
                          "+f"(acc[mt][nt][2]), "+f"(acc[mt][nt][3])
                        : "r"(af[mt][0]), "r"(af[mt][1]), "r"(af[mt][2]), "r"(af[mt][3]),
                          "r"(bf[nt][0]), "r"(bf[nt][1]));
        }
        __syncthreads();
    }

    // epilogue
    float* Cb = C + (long long)blockIdx.z * sC
                  + (long long)(blockIdx.y * BM + wm * 64) * ldc + blockIdx.x * BN + wn * 64;
    const float* Rb = R ? (R + (long long)blockIdx.z * sR
                  + (long long)(blockIdx.y * BM + wm * 64) * ldc + blockIdx.x * BN + wn * 64)
                        : nullptr;

    #pragma unroll
    for (int mt = 0; mt < 4; mt++) {
        #pragma unroll
        for (int nt = 0; nt < 8; nt++) {
            const int r0 = mt * 16 + g;
            const int c0 = nt * 8 + t * 2;
            float v0 = acc[mt][nt][0] * scale;
            float v1 = acc[mt][nt][1] * scale;
            float v2 = acc[mt][nt][2] * scale;
            float v3 = acc[mt][nt][3] * scale;
            if (Rb) {
                v0 += Rb[(long long)r0 * ldc + c0];
                v1 += Rb[(long long)r0 * ldc + c0 + 1];
                v2 += Rb[(long long)(r0 + 8) * ldc + c0];
                v3 += Rb[(long long)(r0 + 8) * ldc + c0 + 1];
            }
            if (round_out) {
                v0 = round_tf32(v0); v1 = round_tf32(v1);
                v2 = round_tf32(v2); v3 = round_tf32(v3);
            }
            *(float2*)&Cb[(long long)r0 * ldc + c0]       = make_float2(v0, v1);
            *(float2*)&Cb[(long long)(r0 + 8) * ldc + c0] = make_float2(v2, v3);
        }
    }
}

// ---------------- round fp32 array to tf32 (rna) ----------------
__global__ void __launch_bounds__(256) round_arr(const float* __restrict__ in,
                                                 float* __restrict__ out)
{
    long long i = ((long long)blockIdx.x * 256 + threadIdx.x) * 4;
    float4 v = *(const float4*)&in[i];
    v.x = round_tf32(v.x); v.y = round_tf32(v.y);
    v.z = round_tf32(v.z); v.w = round_tf32(v.w);
    *(float4*)&out[i] = v;
}

// ---------------- transpose: vt[b][n][j] = v[b][j][n] ----------------
__global__ void __launch_bounds__(256) transpose_v(const float* __restrict__ v,
                                                   float* __restrict__ vt)
{
    __shared__ float t[32][33];
    const long long bi = (long long)blockIdx.z * SEQ * DIM;
    const long long bo = (long long)blockIdx.z * DIM * SEQ;
    int x = blockIdx.x * 32 + threadIdx.x;   // n
    int y = blockIdx.y * 32 + threadIdx.y;   // j
    #pragma unroll
    for (int i = 0; i < 32; i += 8)
        t[threadIdx.y + i][threadIdx.x] = v[bi + (long long)(y + i) * DIM + x];
    __syncthreads();
    int xo = blockIdx.y * 32 + threadIdx.x;  // j
    int yo = blockIdx.x * 32 + threadIdx.y;  // n
    #pragma unroll
    for (int i = 0; i < 32; i += 8)
        vt[bo + (long long)(yo + i) * SEQ + xo] = t[threadIdx.x][threadIdx.y + i];
}

// ---------------- row softmax (2048 cols), writes tf32-rounded probs --------
__global__ void __launch_bounds__(256) softmax_rows(float* __restrict__ S)
{
    long long row = blockIdx.x;
    float* p = S + row * SEQ;
    int tid = threadIdx.x;
    __shared__ float red[256];

    float v[8];
    float mx = -INFINITY;
    #pragma unroll
    for (int i = 0; i < 8; i++) { v[i] = p[tid + i * 256]; mx = fmaxf(mx, v[i]); }
    red[tid] = mx; __syncthreads();
    #pragma unroll
    for (int s = 128; s > 0; s >>= 1) { if (tid < s) red[tid] = fmaxf(red[tid], red[tid + s]); __syncthreads(); }
    mx = red[0]; __syncthreads();

    float sum = 0.f;
    #pragma unroll
    for (int i = 0; i < 8; i++) { v[i] = __expf(v[i] - mx); sum += v[i]; }
    red[tid] = sum; __syncthreads();
    #pragma unroll
    for (int s = 128; s > 0; s >>= 1) { if (tid < s) red[tid] += red[tid + s]; __syncthreads(); }
    float inv = 1.0f / red[0];
    #pragma unroll
    for (int i = 0; i < 8; i++) p[tid + i * 256] = round_tf32(v[i] * inv);
}

extern "C" void kernel_launch(void* const* d_in, const int* in_sizes, int n_in,
                              void* d_out, int out_size)
{
    const float* x  = (const float*)d_in[0];
    const float* Wq = (const float*)d_in[1];
    const float* Wk = (const float*)d_in[2];
    const float* Wv = (const float*)d_in[3];
    float* out = (float*)d_out;

    float *q, *k, *v, *vt, *s, *xr, *wq, *wk, *wv;
    cudaGetSymbolAddress((void**)&q,  g_q);
    cudaGetSymbolAddress((void**)&k,  g_k);
    cudaGetSymbolAddress((void**)&v,  g_v);
    cudaGetSymbolAddress((void**)&vt, g_vt);
    cudaGetSymbolAddress((void**)&s,  g_s);
    cudaGetSymbolAddress((void**)&xr, g_xr);
    cudaGetSymbolAddress((void**)&wq, g_wq);
    cudaGetSymbolAddress((void**)&wk, g_wk);
    cudaGetSymbolAddress((void**)&wv, g_wv);

    cudaFuncSetAttribute(mma_gemm_nt, cudaFuncAttributeMaxDynamicSharedMemorySize, SMEM_BYTES);

    const int M = BATCH * SEQ;   // 8192

    // Pre-round inputs to tf32 (rna, unbiased)
    round_arr<<<(M * DIM) / 1024, 256>>>(x, xr);
    round_arr<<<(DIM * DIM) / 1024, 256>>>(Wq, wq);
    round_arr<<<(DIM * DIM) / 1024, 256>>>(Wk, wk);
    round_arr<<<(DIM * DIM) / 1024, 256>>>(Wv, wv);

    // QKV projections: [8192,1024] = xr @ W^T, K=1024 (32 k-tiles), round outputs
    dim3 gP(DIM / BN, M / BM, 1);   // (8, 32)
    mma_gemm_nt<<<gP, 256, SMEM_BYTES>>>(xr, wq, nullptr, q, DIM, DIM, DIM, 32, 1.0f, 1, 0, 0, 0, 0);
    mma_gemm_nt<<<gP, 256, SMEM_BYTES>>>(xr, wk, nullptr, k, DIM, DIM, DIM, 32, 1.0f, 1, 0, 0, 0, 0);
    mma_gemm_nt<<<gP, 256, SMEM_BYTES>>>(xr, wv, nullptr, v, DIM, DIM, DIM, 32, 1.0f, 1, 0, 0, 0, 0);

    // V transpose for PV gemm
    dim3 gT(DIM / 32, SEQ / 32, BATCH);
    transpose_v<<<gT, dim3(32, 8)>>>(v, vt);

    // Scores: per batch S = (1/32) q @ k^T, [2048,2048], K=1024
    dim3 gS(SEQ / BN, SEQ / BM, BATCH);   // (16, 8, 4)
    mma_gemm_nt<<<gS, 256, SMEM_BYTES>>>(q, k, nullptr, s, DIM, DIM, SEQ, 32, 0.03125f, 0,
                                         (long long)SEQ * DIM, (long long)SEQ * DIM, 0,
                                         (long long)SEQ * SEQ);

    // Softmax (writes tf32-rounded probabilities)
    softmax_rows<<<BATCH * SEQ, 256>>>(s);

    // Output: att = S @ v + v  ->  NT with B = vt [1024 x 2048], K=2048 (64 k-tiles)
    dim3 gO(DIM / BN, SEQ / BM, BATCH);   // (8, 8, 4)
    mma_gemm_nt<<<gO, 256, SMEM_BYTES>>>(s, vt, v, out, SEQ, SEQ, DIM, 64, 1.0f, 0,
                                         (long long)SEQ * SEQ, (long long)DIM * SEQ,
                                         (long long)SEQ * DIM, (long long)SEQ * DIM);
}